// round 3
// baseline (speedup 1.0000x reference)
#include <cuda_runtime.h>

// IntDVF scaling-and-squaring, padded-AoS (float4) version.
// ddf0 = dvf / 2^7 ; repeat 7x: ddf = ddf + warp(ddf, ddf)
//
// Field stored as float4 (x,y,z,unused): one LDG.128 per trilinear corner
// fetches all 3 channels -> 8 gather loads + 1 center load + 1 store per voxel.

#define D     128
#define D2    (D * D)
#define D3    (D * D * D)
#define NVOX  (2 * D3)          // 4,194,304 voxels (batch=2)
#define NT    256

// Two 67 MB float4 ping-pong buffers (allocation-free: __device__ globals).
__device__ float4 g_a[(size_t)NVOX];
__device__ float4 g_b[(size_t)NVOX];

__global__ __launch_bounds__(NT)
void pack_f4(const float* __restrict__ in, float4* __restrict__ out) {
    int i = blockIdx.x * NT + threadIdx.x;
    size_t o = (size_t)i * 3;
    out[i] = make_float4(in[o + 0], in[o + 1], in[o + 2], 0.0f);
}

template<bool OUT_AOS>
__global__ __launch_bounds__(NT)
void intdvf_step(const float4* __restrict__ src, void* __restrict__ dst_raw,
                 float scale) {
    int idx = blockIdx.x * NT + threadIdx.x;
    int z = idx & (D - 1);
    int y = (idx >> 7) & (D - 1);
    int x = (idx >> 14) & (D - 1);
    int b = idx >> 21;

    float4 ctr = src[idx];                 // coalesced 16B center read

    float lx = (float)x + ctr.x * scale;
    float ly = (float)y + ctr.y * scale;
    float lz = (float)z + ctr.z * scale;

    float fx = floorf(lx), fy = floorf(ly), fz = floorf(lz);
    float wx1 = lx - fx, wy1 = ly - fy, wz1 = lz - fz;
    float wx0 = 1.0f - wx1, wy0 = 1.0f - wy1, wz0 = 1.0f - wz1;

    int jx = (int)fx, jy = (int)fy, jz = (int)fz;
    int ix0 = min(max(jx,     0), D - 1);
    int ix1 = min(max(jx + 1, 0), D - 1);
    int iy0 = min(max(jy,     0), D - 1);
    int iy1 = min(max(jy + 1, 0), D - 1);
    int iz0 = min(max(jz,     0), D - 1);
    int iz1 = min(max(jz + 1, 0), D - 1);

    int bb  = b * D3;
    int p00 = bb + ix0 * D2 + iy0 * D;
    int p01 = bb + ix0 * D2 + iy1 * D;
    int p10 = bb + ix1 * D2 + iy0 * D;
    int p11 = bb + ix1 * D2 + iy1 * D;

    // 8 corner fetches, each LDG.128 carries all 3 channels.
    float4 v000 = __ldg(src + p00 + iz0);
    float4 v001 = __ldg(src + p00 + iz1);
    float4 v010 = __ldg(src + p01 + iz0);
    float4 v011 = __ldg(src + p01 + iz1);
    float4 v100 = __ldg(src + p10 + iz0);
    float4 v101 = __ldg(src + p10 + iz1);
    float4 v110 = __ldg(src + p11 + iz0);
    float4 v111 = __ldg(src + p11 + iz1);

    float w00 = wx0 * wy0, w01 = wx0 * wy1, w10 = wx1 * wy0, w11 = wx1 * wy1;
    float w000 = w00 * wz0, w001 = w00 * wz1;
    float w010 = w01 * wz0, w011 = w01 * wz1;
    float w100 = w10 * wz0, w101 = w10 * wz1;
    float w110 = w11 * wz0, w111 = w11 * wz1;

    float ax = w000 * v000.x;
    float ay = w000 * v000.y;
    float az = w000 * v000.z;
    ax = fmaf(w001, v001.x, ax); ay = fmaf(w001, v001.y, ay); az = fmaf(w001, v001.z, az);
    ax = fmaf(w010, v010.x, ax); ay = fmaf(w010, v010.y, ay); az = fmaf(w010, v010.z, az);
    ax = fmaf(w011, v011.x, ax); ay = fmaf(w011, v011.y, ay); az = fmaf(w011, v011.z, az);
    ax = fmaf(w100, v100.x, ax); ay = fmaf(w100, v100.y, ay); az = fmaf(w100, v100.z, az);
    ax = fmaf(w101, v101.x, ax); ay = fmaf(w101, v101.y, ay); az = fmaf(w101, v101.z, az);
    ax = fmaf(w110, v110.x, ax); ay = fmaf(w110, v110.y, ay); az = fmaf(w110, v110.z, az);
    ax = fmaf(w111, v111.x, ax); ay = fmaf(w111, v111.y, ay); az = fmaf(w111, v111.z, az);

    // out = scale*(center + interp)   (scale folds the /2^7 init into step 1)
    float ox = scale * (ctr.x + ax);
    float oy = scale * (ctr.y + ay);
    float oz = scale * (ctr.z + az);

    if (OUT_AOS) {
        float* dst = (float*)dst_raw;
        size_t o = (size_t)idx * 3;
        dst[o + 0] = ox;
        dst[o + 1] = oy;
        dst[o + 2] = oz;
    } else {
        ((float4*)dst_raw)[idx] = make_float4(ox, oy, oz, 0.0f);
    }
}

extern "C" void kernel_launch(void* const* d_in, const int* in_sizes, int n_in,
                              void* d_out, int out_size) {
    const float* dvf = (const float*)d_in[0];

    float4* A = nullptr;
    float4* Bf = nullptr;
    cudaGetSymbolAddress((void**)&A,  g_a);
    cudaGetSymbolAddress((void**)&Bf, g_b);

    const int nblocks = NVOX / NT;
    const float s0 = 1.0f / 128.0f;   // 1 / 2^NUM_STEPS

    pack_f4<<<nblocks, NT>>>(dvf, A);

    intdvf_step<false><<<nblocks, NT>>>(A,  Bf,   s0);   // step 1 (fused /128)
    intdvf_step<false><<<nblocks, NT>>>(Bf, A,    1.0f); // step 2
    intdvf_step<false><<<nblocks, NT>>>(A,  Bf,   1.0f); // step 3
    intdvf_step<false><<<nblocks, NT>>>(Bf, A,    1.0f); // step 4
    intdvf_step<false><<<nblocks, NT>>>(A,  Bf,   1.0f); // step 5
    intdvf_step<false><<<nblocks, NT>>>(Bf, A,    1.0f); // step 6
    intdvf_step<true ><<<nblocks, NT>>>(A,  d_out, 1.0f); // step 7 -> AoS d_out
}

// round 7
// speedup vs baseline: 1.1105x; 1.1105x over previous
#include <cuda_runtime.h>
#include <cuda_fp16.h>

// IntDVF scaling-and-squaring, fp16-storage SoA version.
// ddf0 = dvf / 2^7 ; repeat 7x: ddf = ddf + warp(ddf, ddf)
//
// Intermediates stored channel-planar fp16 (25 MB/buffer -> both ping-pong
// buffers L2-resident). All arithmetic in fp32; fp16 is storage only.
// Final step reads fp16 and writes fp32 AoS to d_out.

#define D     128
#define D2    (D * D)
#define D3    (D * D * D)
#define NVOX  (2 * D3)          // 4,194,304 voxels (batch=2)
#define NT    256

// Two 25.2 MB fp16 SoA ping-pong buffers (allocation-free: __device__ globals).
__device__ __half g_a[(size_t)NVOX * 3];
__device__ __half g_b[(size_t)NVOX * 3];

__global__ __launch_bounds__(NT)
void pack_h16(const float* __restrict__ in, __half* __restrict__ out) {
    int i = blockIdx.x * NT + threadIdx.x;
    size_t o = (size_t)i * 3;
    out[i]            = __float2half_rn(in[o + 0]);
    out[i + NVOX]     = __float2half_rn(in[o + 1]);
    out[i + 2 * NVOX] = __float2half_rn(in[o + 2]);
}

template<bool OUT_F32_AOS>
__global__ __launch_bounds__(NT)
void intdvf_step(const __half* __restrict__ src, void* __restrict__ dst_raw,
                 float scale) {
    int idx = blockIdx.x * NT + threadIdx.x;
    int z = idx & (D - 1);
    int y = (idx >> 7) & (D - 1);
    int x = (idx >> 14) & (D - 1);
    int b = idx >> 21;

    // Coalesced SoA center reads (fp16 -> fp32).
    float rx = __half2float(src[idx]);
    float ry = __half2float(src[idx + NVOX]);
    float rz = __half2float(src[idx + 2 * NVOX]);

    float lx = (float)x + rx * scale;
    float ly = (float)y + ry * scale;
    float lz = (float)z + rz * scale;

    float fx = floorf(lx), fy = floorf(ly), fz = floorf(lz);
    float wx1 = lx - fx, wy1 = ly - fy, wz1 = lz - fz;
    float wx0 = 1.0f - wx1, wy0 = 1.0f - wy1, wz0 = 1.0f - wz1;

    int jx = (int)fx, jy = (int)fy, jz = (int)fz;
    int ix0 = min(max(jx,     0), D - 1);
    int ix1 = min(max(jx + 1, 0), D - 1);
    int iy0 = min(max(jy,     0), D - 1);
    int iy1 = min(max(jy + 1, 0), D - 1);
    int iz0 = min(max(jz,     0), D - 1);
    int iz1 = min(max(jz + 1, 0), D - 1);

    int bb  = b * D3;
    int pX0 = ix0 * D2, pX1 = ix1 * D2;
    int rY0 = iy0 * D,  rY1 = iy1 * D;

    int i000 = bb + pX0 + rY0 + iz0;
    int i001 = bb + pX0 + rY0 + iz1;
    int i010 = bb + pX0 + rY1 + iz0;
    int i011 = bb + pX0 + rY1 + iz1;
    int i100 = bb + pX1 + rY0 + iz0;
    int i101 = bb + pX1 + rY0 + iz1;
    int i110 = bb + pX1 + rY1 + iz0;
    int i111 = bb + pX1 + rY1 + iz1;

    float w00 = wx0 * wy0, w01 = wx0 * wy1, w10 = wx1 * wy0, w11 = wx1 * wy1;
    float w000 = w00 * wz0, w001 = w00 * wz1;
    float w010 = w01 * wz0, w011 = w01 * wz1;
    float w100 = w10 * wz0, w101 = w10 * wz1;
    float w110 = w11 * wz0, w111 = w11 * wz1;

    float acc[3];
    const float ctr[3] = {rx, ry, rz};

    #pragma unroll
    for (int c = 0; c < 3; c++) {
        const __half* __restrict__ p = src + (size_t)c * NVOX;
        float a;
        a =      w000 * __half2float(__ldg(p + i000));
        a = fmaf(w001,  __half2float(__ldg(p + i001)), a);
        a = fmaf(w010,  __half2float(__ldg(p + i010)), a);
        a = fmaf(w011,  __half2float(__ldg(p + i011)), a);
        a = fmaf(w100,  __half2float(__ldg(p + i100)), a);
        a = fmaf(w101,  __half2float(__ldg(p + i101)), a);
        a = fmaf(w110,  __half2float(__ldg(p + i110)), a);
        a = fmaf(w111,  __half2float(__ldg(p + i111)), a);
        acc[c] = scale * (ctr[c] + a);   // scale folds the /2^7 init into step 1
    }

    if (OUT_F32_AOS) {
        float* dst = (float*)dst_raw;
        size_t o = (size_t)idx * 3;
        dst[o + 0] = acc[0];
        dst[o + 1] = acc[1];
        dst[o + 2] = acc[2];
    } else {
        __half* dst = (__half*)dst_raw;
        dst[idx]            = __float2half_rn(acc[0]);
        dst[idx + NVOX]     = __float2half_rn(acc[1]);
        dst[idx + 2 * NVOX] = __float2half_rn(acc[2]);
    }
}

extern "C" void kernel_launch(void* const* d_in, const int* in_sizes, int n_in,
                              void* d_out, int out_size) {
    const float* dvf = (const float*)d_in[0];

    __half* A = nullptr;
    __half* Bf = nullptr;
    cudaGetSymbolAddress((void**)&A,  g_a);
    cudaGetSymbolAddress((void**)&Bf, g_b);

    const int nblocks = NVOX / NT;
    const float s0 = 1.0f / 128.0f;   // 1 / 2^NUM_STEPS

    pack_h16<<<nblocks, NT>>>(dvf, A);

    intdvf_step<false><<<nblocks, NT>>>(A,  Bf,   s0);    // step 1 (fused /128)
    intdvf_step<false><<<nblocks, NT>>>(Bf, A,    1.0f);  // step 2
    intdvf_step<false><<<nblocks, NT>>>(A,  Bf,   1.0f);  // step 3
    intdvf_step<false><<<nblocks, NT>>>(Bf, A,    1.0f);  // step 4
    intdvf_step<false><<<nblocks, NT>>>(A,  Bf,   1.0f);  // step 5
    intdvf_step<false><<<nblocks, NT>>>(Bf, A,    1.0f);  // step 6
    intdvf_step<true ><<<nblocks, NT>>>(A,  d_out, 1.0f); // step 7 -> fp32 AoS
}

// round 9
// speedup vs baseline: 1.6901x; 1.5220x over previous
#include <cuda_runtime.h>
#include <cuda_fp16.h>

// IntDVF scaling-and-squaring, packed-half4 (8B/voxel) version.
// ddf0 = dvf / 2^7 ; repeat 7x: ddf = ddf + warp(ddf, ddf)
//
// Field stored as 4x fp16 (x,y,z,pad) = 8 bytes per voxel. One LDG.64 per
// trilinear corner fetches all 3 channels -> 10 L1 instructions per voxel
// (8 gathers + 1 center + 1 store) vs 30 in the scalar-SoA version.
// All arithmetic fp32; fp16 is storage only. Final step writes fp32 AoS.

#define D     128
#define D2    (D * D)
#define D3    (D * D * D)
#define NVOX  (2 * D3)          // 4,194,304 voxels (batch=2)
#define NT    256

// Two 33.5 MB packed ping-pong buffers (both L2-resident together).
__device__ uint2 g_a[(size_t)NVOX];
__device__ uint2 g_b[(size_t)NVOX];

__device__ __forceinline__ uint2 packh4(float x, float y, float z) {
    __half2 xy = __floats2half2_rn(x, y);
    __half2 zw = __floats2half2_rn(z, 0.0f);
    uint2 r;
    r.x = *(const unsigned int*)&xy;
    r.y = *(const unsigned int*)&zw;
    return r;
}

__device__ __forceinline__ void unpackh4(uint2 v, float& x, float& y, float& z) {
    __half2 xy = *(const __half2*)&v.x;
    __half2 zw = *(const __half2*)&v.y;
    float2 f = __half22float2(xy);
    x = f.x;
    y = f.y;
    z = __half2float(__low2half(zw));
}

__global__ __launch_bounds__(NT)
void pack_h4(const float* __restrict__ in, uint2* __restrict__ out) {
    int i = blockIdx.x * NT + threadIdx.x;
    size_t o = (size_t)i * 3;
    out[i] = packh4(in[o + 0], in[o + 1], in[o + 2]);
}

template<bool OUT_F32_AOS>
__global__ __launch_bounds__(NT)
void intdvf_step(const uint2* __restrict__ src, void* __restrict__ dst_raw,
                 float scale) {
    int idx = blockIdx.x * NT + threadIdx.x;
    int z = idx & (D - 1);
    int y = (idx >> 7) & (D - 1);
    int x = (idx >> 14) & (D - 1);
    int b = idx >> 21;

    float rx, ry, rz;
    unpackh4(src[idx], rx, ry, rz);        // coalesced 8B center read

    float lx = (float)x + rx * scale;
    float ly = (float)y + ry * scale;
    float lz = (float)z + rz * scale;

    float fx = floorf(lx), fy = floorf(ly), fz = floorf(lz);
    float wx1 = lx - fx, wy1 = ly - fy, wz1 = lz - fz;
    float wx0 = 1.0f - wx1, wy0 = 1.0f - wy1, wz0 = 1.0f - wz1;

    int jx = (int)fx, jy = (int)fy, jz = (int)fz;
    int ix0 = min(max(jx,     0), D - 1);
    int ix1 = min(max(jx + 1, 0), D - 1);
    int iy0 = min(max(jy,     0), D - 1);
    int iy1 = min(max(jy + 1, 0), D - 1);
    int iz0 = min(max(jz,     0), D - 1);
    int iz1 = min(max(jz + 1, 0), D - 1);

    int bb  = b * D3;
    int p00 = bb + ix0 * D2 + iy0 * D;
    int p01 = bb + ix0 * D2 + iy1 * D;
    int p10 = bb + ix1 * D2 + iy0 * D;
    int p11 = bb + ix1 * D2 + iy1 * D;

    // 8 corner fetches; each LDG.64 carries all 3 channels.
    uint2 v000 = __ldg(src + p00 + iz0);
    uint2 v001 = __ldg(src + p00 + iz1);
    uint2 v010 = __ldg(src + p01 + iz0);
    uint2 v011 = __ldg(src + p01 + iz1);
    uint2 v100 = __ldg(src + p10 + iz0);
    uint2 v101 = __ldg(src + p10 + iz1);
    uint2 v110 = __ldg(src + p11 + iz0);
    uint2 v111 = __ldg(src + p11 + iz1);

    float w00 = wx0 * wy0, w01 = wx0 * wy1, w10 = wx1 * wy0, w11 = wx1 * wy1;
    float w000 = w00 * wz0, w001 = w00 * wz1;
    float w010 = w01 * wz0, w011 = w01 * wz1;
    float w100 = w10 * wz0, w101 = w10 * wz1;
    float w110 = w11 * wz0, w111 = w11 * wz1;

    float ax = 0.f, ay = 0.f, az = 0.f;
    float tx, ty, tz;
    unpackh4(v000, tx, ty, tz); ax = fmaf(w000, tx, ax); ay = fmaf(w000, ty, ay); az = fmaf(w000, tz, az);
    unpackh4(v001, tx, ty, tz); ax = fmaf(w001, tx, ax); ay = fmaf(w001, ty, ay); az = fmaf(w001, tz, az);
    unpackh4(v010, tx, ty, tz); ax = fmaf(w010, tx, ax); ay = fmaf(w010, ty, ay); az = fmaf(w010, tz, az);
    unpackh4(v011, tx, ty, tz); ax = fmaf(w011, tx, ax); ay = fmaf(w011, ty, ay); az = fmaf(w011, tz, az);
    unpackh4(v100, tx, ty, tz); ax = fmaf(w100, tx, ax); ay = fmaf(w100, ty, ay); az = fmaf(w100, tz, az);
    unpackh4(v101, tx, ty, tz); ax = fmaf(w101, tx, ax); ay = fmaf(w101, ty, ay); az = fmaf(w101, tz, az);
    unpackh4(v110, tx, ty, tz); ax = fmaf(w110, tx, ax); ay = fmaf(w110, ty, ay); az = fmaf(w110, tz, az);
    unpackh4(v111, tx, ty, tz); ax = fmaf(w111, tx, ax); ay = fmaf(w111, ty, ay); az = fmaf(w111, tz, az);

    // out = scale*(center + interp)   (scale folds the /2^7 init into step 1)
    float ox = scale * (rx + ax);
    float oy = scale * (ry + ay);
    float oz = scale * (rz + az);

    if (OUT_F32_AOS) {
        float* dst = (float*)dst_raw;
        size_t o = (size_t)idx * 3;
        dst[o + 0] = ox;
        dst[o + 1] = oy;
        dst[o + 2] = oz;
    } else {
        ((uint2*)dst_raw)[idx] = packh4(ox, oy, oz);
    }
}

extern "C" void kernel_launch(void* const* d_in, const int* in_sizes, int n_in,
                              void* d_out, int out_size) {
    const float* dvf = (const float*)d_in[0];

    uint2* A = nullptr;
    uint2* Bf = nullptr;
    cudaGetSymbolAddress((void**)&A,  g_a);
    cudaGetSymbolAddress((void**)&Bf, g_b);

    const int nblocks = NVOX / NT;
    const float s0 = 1.0f / 128.0f;   // 1 / 2^NUM_STEPS

    pack_h4<<<nblocks, NT>>>(dvf, A);

    intdvf_step<false><<<nblocks, NT>>>(A,  Bf,   s0);    // step 1 (fused /128)
    intdvf_step<false><<<nblocks, NT>>>(Bf, A,    1.0f);  // step 2
    intdvf_step<false><<<nblocks, NT>>>(A,  Bf,   1.0f);  // step 3
    intdvf_step<false><<<nblocks, NT>>>(Bf, A,    1.0f);  // step 4
    intdvf_step<false><<<nblocks, NT>>>(A,  Bf,   1.0f);  // step 5
    intdvf_step<false><<<nblocks, NT>>>(Bf, A,    1.0f);  // step 6
    intdvf_step<true ><<<nblocks, NT>>>(A,  d_out, 1.0f); // step 7 -> fp32 AoS
}